// round 1
// baseline (speedup 1.0000x reference)
#include <cuda_runtime.h>
#include <cstdint>

// RWKV7 WKV scan.
//   S_t[i,j] = S_{t-1}[i,j]*w_t[j] + (S_{t-1}[i,:]·a_t) * b_t[j] + v_t[i]*k_t[j]
//   y_t[i]   = S_t[i,:]·r_t
// Rows i are independent -> parallelize over (head, row-block).
//
// Grid: 128 CTAs = 32 heads x 4 row-parts (16 rows each).
// Block: 128 threads. 8 lanes per row (each thread owns 8 consecutive j's in
// registers). Per-step head vectors (a,w,b,k,r,v : 6x64 floats) staged in
// SMEM, double-buffered with cp.async prefetch of step t+1 during step t.

#define HH 32
#define NN 64
#define ROWS_PER_CTA 16
#define VEC_FLOATS 384   // 6 * 64

__device__ __forceinline__ void cp_async16(void* smem_dst, const void* gsrc) {
    unsigned saddr = (unsigned)__cvta_generic_to_shared(smem_dst);
    asm volatile("cp.async.ca.shared.global [%0], [%1], 16;\n"
                 :: "r"(saddr), "l"(gsrc) : "memory");
}
__device__ __forceinline__ void cp_async_commit() {
    asm volatile("cp.async.commit_group;\n" ::: "memory");
}
__device__ __forceinline__ void cp_async_wait_all() {
    asm volatile("cp.async.wait_group 0;\n" ::: "memory");
}

__global__ __launch_bounds__(128, 1)
void wkv7_scan_kernel(const float* __restrict__ rP, const float* __restrict__ wP,
                      const float* __restrict__ kP, const float* __restrict__ vP,
                      const float* __restrict__ aP, const float* __restrict__ bP,
                      const float* __restrict__ stateP,
                      float* __restrict__ yOut, float* __restrict__ sOut,
                      int T)
{
    __shared__ float buf[2][VEC_FLOATS];

    const int tid  = threadIdx.x;
    const int h    = blockIdx.x >> 2;        // head
    const int part = blockIdx.x & 3;         // which 16-row slice
    const int iloc = tid >> 3;                // 0..15
    const int i    = part * ROWS_PER_CTA + iloc;   // global row (value dim)
    const int q    = tid & 7;                 // lane within row group
    const int j0   = q * 8;                   // this thread's first key-col

    // ---- load state rows into registers ----
    float s[8];
    {
        const float* sp = stateP + ((size_t)h * NN + i) * NN + j0;
        const float4 s_lo = *reinterpret_cast<const float4*>(sp);
        const float4 s_hi = *reinterpret_cast<const float4*>(sp + 4);
        s[0]=s_lo.x; s[1]=s_lo.y; s[2]=s_lo.z; s[3]=s_lo.w;
        s[4]=s_hi.x; s[5]=s_hi.y; s[6]=s_hi.z; s[7]=s_hi.w;
    }

    // ---- loader thread setup: 96 threads fetch 6*64 floats (one float4 each)
    // SMEM vector layout: a(0), w(64), b(128), k(192), r(256), v(320)
    const float* gbase = nullptr;
    float* sdst[2] = {nullptr, nullptr};
    if (tid < 96) {
        const int which = tid >> 4;   // 0..5
        const int idx   = tid & 15;   // float4 index within 64 floats
        const float* srcs[6] = { aP, wP, bP, kP, rP, vP };
        gbase = srcs[which] + (size_t)h * NN + idx * 4;
        sdst[0] = &buf[0][which * NN + idx * 4];
        sdst[1] = &buf[1][which * NN + idx * 4];
    }

    // preload t = 0
    if (tid < 96) cp_async16(sdst[0], gbase);
    cp_async_commit();
    cp_async_wait_all();
    __syncthreads();

    const size_t stepStride = (size_t)HH * NN;   // 2048 floats per timestep
    float* yRowPtr = yOut + (size_t)h * NN + i;  // advance by stepStride per t

    for (int t = 0; t < T; ++t) {
        const float* B = buf[t & 1];

        // prefetch t+1 into the other buffer (it was consumed in step t-1)
        if (tid < 96 && (t + 1) < T)
            cp_async16(sdst[(t + 1) & 1], gbase + (size_t)(t + 1) * stepStride);
        cp_async_commit();

        // ---- fetch this thread's 8-column slices of the step vectors ----
        float av[8], wv[8], bv[8], kv[8], rv[8];
        {
            const float4* pa = reinterpret_cast<const float4*>(B +   0) + q * 2;
            const float4* pw = reinterpret_cast<const float4*>(B +  64) + q * 2;
            const float4* pb = reinterpret_cast<const float4*>(B + 128) + q * 2;
            const float4* pk = reinterpret_cast<const float4*>(B + 192) + q * 2;
            const float4* pr = reinterpret_cast<const float4*>(B + 256) + q * 2;
            float4 t0, t1;
            t0 = pa[0]; t1 = pa[1];
            av[0]=t0.x; av[1]=t0.y; av[2]=t0.z; av[3]=t0.w; av[4]=t1.x; av[5]=t1.y; av[6]=t1.z; av[7]=t1.w;
            t0 = pw[0]; t1 = pw[1];
            wv[0]=t0.x; wv[1]=t0.y; wv[2]=t0.z; wv[3]=t0.w; wv[4]=t1.x; wv[5]=t1.y; wv[6]=t1.z; wv[7]=t1.w;
            t0 = pb[0]; t1 = pb[1];
            bv[0]=t0.x; bv[1]=t0.y; bv[2]=t0.z; bv[3]=t0.w; bv[4]=t1.x; bv[5]=t1.y; bv[6]=t1.z; bv[7]=t1.w;
            t0 = pk[0]; t1 = pk[1];
            kv[0]=t0.x; kv[1]=t0.y; kv[2]=t0.z; kv[3]=t0.w; kv[4]=t1.x; kv[5]=t1.y; kv[6]=t1.z; kv[7]=t1.w;
            t0 = pr[0]; t1 = pr[1];
            rv[0]=t0.x; rv[1]=t0.y; rv[2]=t0.z; rv[3]=t0.w; rv[4]=t1.x; rv[5]=t1.y; rv[6]=t1.z; rv[7]=t1.w;
        }
        const float vi = B[320 + i];

        // ---- sa = S[i,:] . a  (partial in-thread, then 8-lane xor reduce) ----
        float p0 = s[0] * av[0];
        float p1 = s[1] * av[1];
        p0 = fmaf(s[2], av[2], p0);
        p1 = fmaf(s[3], av[3], p1);
        p0 = fmaf(s[4], av[4], p0);
        p1 = fmaf(s[5], av[5], p1);
        p0 = fmaf(s[6], av[6], p0);
        p1 = fmaf(s[7], av[7], p1);
        float sa = p0 + p1;
        sa += __shfl_xor_sync(0xffffffffu, sa, 1);
        sa += __shfl_xor_sync(0xffffffffu, sa, 2);
        sa += __shfl_xor_sync(0xffffffffu, sa, 4);

        // ---- state update + y partial ----
        float y0 = 0.f, y1 = 0.f;
        #pragma unroll
        for (int j = 0; j < 8; ++j) {
            float tmp = vi * kv[j];
            tmp = fmaf(sa, bv[j], tmp);
            s[j] = fmaf(s[j], wv[j], tmp);
            if (j & 1) y1 = fmaf(s[j], rv[j], y1);
            else       y0 = fmaf(s[j], rv[j], y0);
        }
        float y = y0 + y1;
        y += __shfl_xor_sync(0xffffffffu, y, 1);
        y += __shfl_xor_sync(0xffffffffu, y, 2);
        y += __shfl_xor_sync(0xffffffffu, y, 4);
        if (q == 0) yRowPtr[(size_t)t * stepStride] = y;

        // ensure prefetch landed before anyone reads next buffer
        cp_async_wait_all();
        __syncthreads();
    }

    // ---- write final state ----
    {
        float* op = sOut + ((size_t)h * NN + i) * NN + j0;
        float4 lo, hi;
        lo.x=s[0]; lo.y=s[1]; lo.z=s[2]; lo.w=s[3];
        hi.x=s[4]; hi.y=s[5]; hi.z=s[6]; hi.w=s[7];
        *reinterpret_cast<float4*>(op)     = lo;
        *reinterpret_cast<float4*>(op + 4) = hi;
    }
}

extern "C" void kernel_launch(void* const* d_in, const int* in_sizes, int n_in,
                              void* d_out, int out_size)
{
    const float* r  = (const float*)d_in[0];
    const float* w  = (const float*)d_in[1];
    const float* k  = (const float*)d_in[2];
    const float* v  = (const float*)d_in[3];
    const float* a  = (const float*)d_in[4];
    const float* b  = (const float*)d_in[5];
    const float* st = (const float*)d_in[6];

    const int T = in_sizes[0] / (HH * NN);

    float* y    = (float*)d_out;
    float* sfin = y + (size_t)T * HH * NN;

    wkv7_scan_kernel<<<HH * 4, 128>>>(r, w, k, v, a, b, st, y, sfin, T);
}

// round 2
// speedup vs baseline: 2.5975x; 2.5975x over previous
#include <cuda_runtime.h>
#include <cstdint>

// RWKV7 WKV scan.
//   sa_t[i]   = S_{t-1}[i,:] . a_t
//   S_t[i,j]  = S_{t-1}[i,j]*w_t[j] + sa_t[i]*b_t[j] + v_t[i]*k_t[j]
//   y_t[i]    = S_t[i,:] . r_t
// Rows i independent -> 32 heads x 64 rows = 2048 independent scans.
//
// Grid: 128 CTAs = 32 heads x 4 row-parts (16 rows each).
// Block: 128 threads; 8 lanes per row, 8 j's per thread in registers.
// Per-step head vectors (a,w,b,k,r,v : 6x64 f32) staged in SMEM through a
// 4-deep cp.async pipeline (prefetch distance 3, wait_group 2) so the global
// load latency is fully off the recurrence critical path.
// y-reduction of step t is deferred to step t+1 so its shuffle chain
// interleaves with the sa shuffle chain (both depend only on S_t).

#define HH 32
#define NN 64
#define ROWS_PER_CTA 16
#define VEC_FLOATS 384   // 6 * 64
#define NBUF 4

__device__ __forceinline__ void cp_async16(void* smem_dst, const void* gsrc) {
    unsigned saddr = (unsigned)__cvta_generic_to_shared(smem_dst);
    asm volatile("cp.async.ca.shared.global [%0], [%1], 16;\n"
                 :: "r"(saddr), "l"(gsrc) : "memory");
}
__device__ __forceinline__ void cp_async_commit() {
    asm volatile("cp.async.commit_group;\n" ::: "memory");
}
__device__ __forceinline__ void cp_async_wait2() {
    asm volatile("cp.async.wait_group 2;\n" ::: "memory");
}

__global__ __launch_bounds__(128, 1)
void wkv7_scan_kernel(const float* __restrict__ rP, const float* __restrict__ wP,
                      const float* __restrict__ kP, const float* __restrict__ vP,
                      const float* __restrict__ aP, const float* __restrict__ bP,
                      const float* __restrict__ stateP,
                      float* __restrict__ yOut, float* __restrict__ sOut,
                      int T)
{
    __shared__ float buf[NBUF][VEC_FLOATS];

    const int tid  = threadIdx.x;
    const int h    = blockIdx.x >> 2;              // head
    const int part = blockIdx.x & 3;               // 16-row slice
    const int iloc = tid >> 3;                     // 0..15
    const int i    = part * ROWS_PER_CTA + iloc;   // global row (value dim)
    const int q    = tid & 7;                      // lane within row group
    const int j0   = q * 8;                        // first key-col owned

    // ---- state rows into registers ----
    float s[8];
    {
        const float* sp = stateP + ((size_t)h * NN + i) * NN + j0;
        const float4 s_lo = *reinterpret_cast<const float4*>(sp);
        const float4 s_hi = *reinterpret_cast<const float4*>(sp + 4);
        s[0]=s_lo.x; s[1]=s_lo.y; s[2]=s_lo.z; s[3]=s_lo.w;
        s[4]=s_hi.x; s[5]=s_hi.y; s[6]=s_hi.z; s[7]=s_hi.w;
    }

    // ---- loader setup: 96 threads fetch 6*64 floats (one float4 each) ----
    // SMEM vector layout within a buffer: a(0), w(64), b(128), k(192), r(256), v(320)
    const float* gbase = nullptr;
    int loff = 0;
    const bool isLoader = (tid < 96);
    if (isLoader) {
        const int which = tid >> 4;   // 0..5
        const int idx   = tid & 15;   // float4 index within 64 floats
        const float* srcs[6] = { aP, wP, bP, kP, rP, vP };
        gbase = srcs[which] + (size_t)h * NN + idx * 4;
        loff  = which * NN + idx * 4;
    }

    const size_t stepStride = (size_t)HH * NN;   // 2048 floats per timestep
    float* yRowPtr = yOut + (size_t)h * NN + i;

    // ---- prologue: prefetch steps 0,1,2 as 3 separate groups ----
    #pragma unroll
    for (int p = 0; p < 3; ++p) {
        if (isLoader && p < T)
            cp_async16(&buf[p][loff], gbase + (size_t)p * stepStride);
        cp_async_commit();
    }

    float py0 = 0.f, py1 = 0.f;   // deferred y partials from previous step

    for (int t = 0; t < T; ++t) {
        // group for step t is complete once <=2 groups remain outstanding
        cp_async_wait2();
        __syncthreads();

        // prefetch step t+3 into buffer (t+3)%4 (== slot of t-1, already consumed)
        if (isLoader && (t + 3) < T)
            cp_async16(&buf[(t + 3) & 3][loff], gbase + (size_t)(t + 3) * stepStride);
        cp_async_commit();

        const float* B = buf[t & 3];

        // ---- this thread's 8-column slices ----
        float av[8], wv[8], bv[8], kv[8], rv[8];
        {
            const float4* pa = reinterpret_cast<const float4*>(B +   0) + q * 2;
            const float4* pw = reinterpret_cast<const float4*>(B +  64) + q * 2;
            const float4* pb = reinterpret_cast<const float4*>(B + 128) + q * 2;
            const float4* pk = reinterpret_cast<const float4*>(B + 192) + q * 2;
            const float4* pr = reinterpret_cast<const float4*>(B + 256) + q * 2;
            float4 t0, t1;
            t0 = pa[0]; t1 = pa[1];
            av[0]=t0.x; av[1]=t0.y; av[2]=t0.z; av[3]=t0.w; av[4]=t1.x; av[5]=t1.y; av[6]=t1.z; av[7]=t1.w;
            t0 = pw[0]; t1 = pw[1];
            wv[0]=t0.x; wv[1]=t0.y; wv[2]=t0.z; wv[3]=t0.w; wv[4]=t1.x; wv[5]=t1.y; wv[6]=t1.z; wv[7]=t1.w;
            t0 = pb[0]; t1 = pb[1];
            bv[0]=t0.x; bv[1]=t0.y; bv[2]=t0.z; bv[3]=t0.w; bv[4]=t1.x; bv[5]=t1.y; bv[6]=t1.z; bv[7]=t1.w;
            t0 = pk[0]; t1 = pk[1];
            kv[0]=t0.x; kv[1]=t0.y; kv[2]=t0.z; kv[3]=t0.w; kv[4]=t1.x; kv[5]=t1.y; kv[6]=t1.z; kv[7]=t1.w;
            t0 = pr[0]; t1 = pr[1];
            rv[0]=t0.x; rv[1]=t0.y; rv[2]=t0.z; rv[3]=t0.w; rv[4]=t1.x; rv[5]=t1.y; rv[6]=t1.z; rv[7]=t1.w;
        }
        const float vi = B[320 + i];

        // ---- sa partials (on critical path) ----
        float p0 = s[0] * av[0];
        float p1 = s[1] * av[1];
        p0 = fmaf(s[2], av[2], p0);
        p1 = fmaf(s[3], av[3], p1);
        p0 = fmaf(s[4], av[4], p0);
        p1 = fmaf(s[5], av[5], p1);
        p0 = fmaf(s[6], av[6], p0);
        p1 = fmaf(s[7], av[7], p1);
        float sa = p0 + p1;

        // ---- two independent shuffle chains: sa(t) and y(t-1); interleave ----
        float yv = py0 + py1;
        sa += __shfl_xor_sync(0xffffffffu, sa, 1);
        yv += __shfl_xor_sync(0xffffffffu, yv, 1);
        sa += __shfl_xor_sync(0xffffffffu, sa, 2);
        yv += __shfl_xor_sync(0xffffffffu, yv, 2);
        sa += __shfl_xor_sync(0xffffffffu, sa, 4);
        yv += __shfl_xor_sync(0xffffffffu, yv, 4);

        if (t > 0 && q == 0)
            yRowPtr[(size_t)(t - 1) * stepStride] = yv;

        // ---- state update + y partials (reduced next iteration) ----
        float y0 = 0.f, y1 = 0.f;
        #pragma unroll
        for (int j = 0; j < 8; ++j) {
            float tmp = vi * kv[j];
            tmp = fmaf(sa, bv[j], tmp);
            s[j] = fmaf(s[j], wv[j], tmp);
            if (j & 1) y1 = fmaf(s[j], rv[j], y1);
            else       y0 = fmaf(s[j], rv[j], y0);
        }
        py0 = y0; py1 = y1;
    }

    // ---- epilogue: reduce + store y for t = T-1 ----
    {
        float yv = py0 + py1;
        yv += __shfl_xor_sync(0xffffffffu, yv, 1);
        yv += __shfl_xor_sync(0xffffffffu, yv, 2);
        yv += __shfl_xor_sync(0xffffffffu, yv, 4);
        if (q == 0)
            yRowPtr[(size_t)(T - 1) * stepStride] = yv;
    }

    // ---- final state ----
    {
        float* op = sOut + ((size_t)h * NN + i) * NN + j0;
        float4 lo, hi;
        lo.x=s[0]; lo.y=s[1]; lo.z=s[2]; lo.w=s[3];
        hi.x=s[4]; hi.y=s[5]; hi.z=s[6]; hi.w=s[7];
        *reinterpret_cast<float4*>(op)     = lo;
        *reinterpret_cast<float4*>(op + 4) = hi;
    }
}

extern "C" void kernel_launch(void* const* d_in, const int* in_sizes, int n_in,
                              void* d_out, int out_size)
{
    const float* r  = (const float*)d_in[0];
    const float* w  = (const float*)d_in[1];
    const float* k  = (const float*)d_in[2];
    const float* v  = (const float*)d_in[3];
    const float* a  = (const float*)d_in[4];
    const float* b  = (const float*)d_in[5];
    const float* st = (const float*)d_in[6];

    const int T = in_sizes[0] / (HH * NN);

    float* y    = (float*)d_out;
    float* sfin = y + (size_t)T * HH * NN;

    wkv7_scan_kernel<<<HH * 4, 128>>>(r, w, k, v, a, b, st, y, sfin, T);
}